// round 7
// baseline (speedup 1.0000x reference)
#include <cuda_runtime.h>
#include <cuda_bf16.h>
#include <cstdint>

// B=4, H=16, S=1024, D=64 fp32. out buffer: out [B,H,S,D] then attn [B,H,S,S]
#define SEQ 1024
#define DH  64
#define BM  128
#define TPB 256
#define NCHUNK 8

// smem word offsets
#define KVF_W 0        // K frags [16nt][4ks][32][4] / V frags [8nt][8ks][32][4] / obuf [128][64] = 8192 w
#define QL_W  8192     // Q lo frags [8rb][4ks][32][4] = 4096 w
#define MFL_W 12288    // mask flags [1024] -> after pass A: stat [2][128] f2 (512 w) + rowstat [128] f2 (256 w @ +512)
#define SM_WORDS 13312
#define SM_BYTES (SM_WORDS * 4)

__device__ __forceinline__ uint32_t bpack(float lo, float hi) {
    uint32_t u;
    asm("cvt.rn.bf16x2.f32 %0, %1, %2;" : "=r"(u) : "f"(hi), "f"(lo));
    return u;
}
__device__ __forceinline__ float bhi(float x) {
    return __bfloat162float(__float2bfloat16(x));
}
__device__ __forceinline__ void mma_bf16(float* d, uint32_t a0, uint32_t a1,
                                         uint32_t a2, uint32_t a3,
                                         uint32_t b0, uint32_t b1) {
    asm volatile(
        "mma.sync.aligned.m16n8k16.row.col.f32.bf16.bf16.f32 "
        "{%0,%1,%2,%3},{%4,%5,%6,%7},{%8,%9},{%0,%1,%2,%3};"
        : "+f"(d[0]), "+f"(d[1]), "+f"(d[2]), "+f"(d[3])
        : "r"(a0), "r"(a1), "r"(a2), "r"(a3), "r"(b0), "r"(b1));
}

__global__ __launch_bounds__(TPB, 2)
void attn_flash_kernel(const float* __restrict__ q,
                       const float* __restrict__ k,
                       const float* __restrict__ v,
                       const float* __restrict__ add_attn,
                       const int*   __restrict__ mask,
                       float* __restrict__ out,
                       float* __restrict__ attn)
{
    extern __shared__ uint32_t smw[];
    float* smf = reinterpret_cast<float*>(smw);

    const int tid  = threadIdx.x;
    const int w    = tid >> 5;
    const int lane = tid & 31;
    const int g    = lane >> 2;
    const int tig  = lane & 3;
    const int wr   = w >> 1;            // row group: 32 rows
    const int wc   = w & 1;             // pass A: key half / pass B: key group
    const int bh   = blockIdx.y;
    const int b    = bh >> 4;
    const int q0   = blockIdx.x * BM;
    const int r0   = wr * 32;

    const float* qbase = q + ((size_t)bh * SEQ + q0) * DH;
    const float* kbase = k + (size_t)bh * SEQ * DH;
    const float* vbase = v + (size_t)bh * SEQ * DH;
    const float* bias0 = add_attn + (size_t)b * SEQ * SEQ + (size_t)q0 * SEQ;
    float* attn0 = attn + ((size_t)bh * SEQ + q0) * SEQ;

    // ---- mask flags ----
    for (int i = tid; i < SEQ; i += TPB)
        smf[MFL_W + i] = mask[b * SEQ + i] ? 1.0f : 0.0f;

    // ---- Q A-fragments: hi in regs (2 row-blocks), lo in shared QL slice ----
    uint4 qh[2][4];
    #pragma unroll
    for (int mt = 0; mt < 2; ++mt) {
        const float* qr0 = qbase + (size_t)(r0 + mt * 16 + g) * DH;
        const float* qr1 = qr0 + (size_t)8 * DH;
        #pragma unroll
        for (int ks = 0; ks < 4; ++ks) {
            float2 x0 = *(const float2*)(qr0 + ks * 16 + 2 * tig);
            float2 x1 = *(const float2*)(qr1 + ks * 16 + 2 * tig);
            float2 x2 = *(const float2*)(qr0 + ks * 16 + 2 * tig + 8);
            float2 x3 = *(const float2*)(qr1 + ks * 16 + 2 * tig + 8);
            x0.x *= 0.125f; x0.y *= 0.125f; x1.x *= 0.125f; x1.y *= 0.125f;
            x2.x *= 0.125f; x2.y *= 0.125f; x3.x *= 0.125f; x3.y *= 0.125f;
            float h0x = bhi(x0.x), h0y = bhi(x0.y), h1x = bhi(x1.x), h1y = bhi(x1.y);
            float h2x = bhi(x2.x), h2y = bhi(x2.y), h3x = bhi(x3.x), h3y = bhi(x3.y);
            qh[mt][ks].x = bpack(h0x, h0y);
            qh[mt][ks].y = bpack(h1x, h1y);
            qh[mt][ks].z = bpack(h2x, h2y);
            qh[mt][ks].w = bpack(h3x, h3y);
            if (wc == 0) {
                uint4 ql;
                ql.x = bpack(x0.x - h0x, x0.y - h0y);
                ql.y = bpack(x1.x - h1x, x1.y - h1y);
                ql.z = bpack(x2.x - h2x, x2.y - h2y);
                ql.w = bpack(x3.x - h3x, x3.y - h3y);
                *(uint4*)&smw[QL_W + (uint32_t)((((wr * 2 + mt) * 4 + ks) * 32 + lane) * 4)] = ql;
            }
        }
    }

    float om[2][2], ol[2][2];
    #pragma unroll
    for (int mt = 0; mt < 2; ++mt)
        #pragma unroll
        for (int h = 0; h < 2; ++h) { om[mt][h] = -3.0e38f; ol[mt][h] = 0.0f; }

    // ================= Pass A: S = QK^T + bias, masked -> attn; online (m,l)
    for (int ct = 0; ct < NCHUNK; ++ct) {
        __syncthreads();
        // stage K chunk (B-frag order, hi/lo interleaved in uint4)
        #pragma unroll
        for (int i = 0; i < 8; ++i) {
            int idx = i * TPB + tid;
            int key = idx >> 4, dg = idx & 15;
            float4 kv = *(const float4*)(kbase + (size_t)(ct * 128 + key) * DH + dg * 4);
            float hx = bhi(kv.x), hy = bhi(kv.y), hz = bhi(kv.z), hw = bhi(kv.w);
            int nt = key >> 3;
            int ks = dg >> 2, c = (dg & 3) * 4;
            int reg = (c & 8) ? 1 : 0;
            int lane0 = (key & 7) * 4 + ((c & 7) >> 1);
            uint32_t base = KVF_W + (uint32_t)(((nt * 4 + ks) * 32 + lane0) * 4);
            smw[base + reg]     = bpack(hx, hy);
            smw[base + 4 + reg] = bpack(hz, hw);
            smw[base + 2 + reg] = bpack(kv.x - hx, kv.y - hy);
            smw[base + 6 + reg] = bpack(kv.z - hz, kv.w - hw);
        }
        __syncthreads();

        float sacc[2][8][4];
        #pragma unroll
        for (int mt = 0; mt < 2; ++mt)
            #pragma unroll
            for (int nt = 0; nt < 8; ++nt)
                #pragma unroll
                for (int r2 = 0; r2 < 4; ++r2) sacc[mt][nt][r2] = 0.0f;

        #pragma unroll
        for (int ks = 0; ks < 4; ++ks) {
            uint4 ql[2];
            #pragma unroll
            for (int mt = 0; mt < 2; ++mt)
                ql[mt] = *(const uint4*)&smw[QL_W +
                    (uint32_t)((((wr * 2 + mt) * 4 + ks) * 32 + lane) * 4)];
            #pragma unroll
            for (int nt = 0; nt < 8; ++nt) {
                uint4 bb = *(const uint4*)&smw[KVF_W +
                    (uint32_t)((((wc * 8 + nt) * 4 + ks) * 32 + lane) * 4)];
                #pragma unroll
                for (int mt = 0; mt < 2; ++mt) {
                    mma_bf16(sacc[mt][nt], qh[mt][ks].x, qh[mt][ks].y,
                             qh[mt][ks].z, qh[mt][ks].w, bb.x, bb.y);
                    mma_bf16(sacc[mt][nt], qh[mt][ks].x, qh[mt][ks].y,
                             qh[mt][ks].z, qh[mt][ks].w, bb.z, bb.w);
                    mma_bf16(sacc[mt][nt], ql[mt].x, ql[mt].y,
                             ql[mt].z, ql[mt].w, bb.x, bb.y);
                }
            }
        }

        // epilogue: bias + mask, write raw s, online (m,l) over this 64-key half
        #pragma unroll
        for (int mt = 0; mt < 2; ++mt) {
            int rA = r0 + mt * 16 + g;
            float ml0 = -3.0e38f, ml1 = -3.0e38f;
            #pragma unroll
            for (int nt = 0; nt < 8; ++nt) {
                int gc = ct * 128 + wc * 64 + nt * 8 + 2 * tig;
                float2 mf = *(const float2*)&smf[MFL_W + gc];
                float2 b0 = *(const float2*)(bias0 + (size_t)rA * SEQ + gc);
                float2 b1 = *(const float2*)(bias0 + (size_t)(rA + 8) * SEQ + gc);
                float s0 = (mf.x != 0.0f) ? sacc[mt][nt][0] + b0.x : -1e9f;
                float s1 = (mf.y != 0.0f) ? sacc[mt][nt][1] + b0.y : -1e9f;
                float s2 = (mf.x != 0.0f) ? sacc[mt][nt][2] + b1.x : -1e9f;
                float s3 = (mf.y != 0.0f) ? sacc[mt][nt][3] + b1.y : -1e9f;
                *(float2*)(attn0 + (size_t)rA * SEQ + gc)       = make_float2(s0, s1);
                *(float2*)(attn0 + (size_t)(rA + 8) * SEQ + gc) = make_float2(s2, s3);
                sacc[mt][nt][0] = s0; sacc[mt][nt][1] = s1;
                sacc[mt][nt][2] = s2; sacc[mt][nt][3] = s3;
                ml0 = fmaxf(ml0, fmaxf(s0, s1));
                ml1 = fmaxf(ml1, fmaxf(s2, s3));
            }
            float mn0 = fmaxf(om[mt][0], ml0), mn1 = fmaxf(om[mt][1], ml1);
            float a0 = 0.0f, a1 = 0.0f;
            #pragma unroll
            for (int nt = 0; nt < 8; ++nt) {
                a0 += __expf(sacc[mt][nt][0] - mn0) + __expf(sacc[mt][nt][1] - mn0);
                a1 += __expf(sacc[mt][nt][2] - mn1) + __expf(sacc[mt][nt][3] - mn1);
            }
            ol[mt][0] = ol[mt][0] * __expf(om[mt][0] - mn0) + a0;  om[mt][0] = mn0;
            ol[mt][1] = ol[mt][1] * __expf(om[mt][1] - mn1) + a1;  om[mt][1] = mn1;
        }
    }

    // ---- merge (m,l): tig lanes, then the two key-halves via smem ----
    __syncthreads();   // mask region now reusable as stat region
    #pragma unroll
    for (int mt = 0; mt < 2; ++mt)
        #pragma unroll
        for (int h = 0; h < 2; ++h) {
            float m = om[mt][h], l = ol[mt][h];
            #pragma unroll
            for (int o = 1; o <= 2; o <<= 1) {
                float mo = __shfl_xor_sync(~0u, m, o);
                float lo_ = __shfl_xor_sync(~0u, l, o);
                float mn = fmaxf(m, mo);
                l = l * __expf(m - mn) + lo_ * __expf(mo - mn);
                m = mn;
            }
            if (tig == 0) {
                int row = r0 + mt * 16 + g + 8 * h;
                *(float2*)&smf[MFL_W + (wc * 128 + row) * 2] = make_float2(m, l);
            }
        }
    __syncthreads();
    if (tid < 128) {
        float2 a = *(const float2*)&smf[MFL_W + tid * 2];
        float2 c = *(const float2*)&smf[MFL_W + (128 + tid) * 2];
        float mn = fmaxf(a.x, c.x);
        float l  = a.y * __expf(a.x - mn) + c.y * __expf(c.x - mn);
        *(float2*)&smf[MFL_W + 512 + tid * 2] = make_float2(mn, 1.0f / l);
    }
    __syncthreads();

    // rowstat for this warp's rows (m, 1/l)
    float2 rs[2][2];
    #pragma unroll
    for (int mt = 0; mt < 2; ++mt)
        #pragma unroll
        for (int h = 0; h < 2; ++h)
            rs[mt][h] = *(const float2*)&smf[MFL_W + 512 + (r0 + mt * 16 + g + 8 * h) * 2];

    // ================= Pass B: p = exp(s-m)/l -> attn; O = P @ V (key-split) ==
    float oacc[2][8][4];
    #pragma unroll
    for (int mt = 0; mt < 2; ++mt)
        #pragma unroll
        for (int nt = 0; nt < 8; ++nt)
            #pragma unroll
            for (int r2 = 0; r2 < 4; ++r2) oacc[mt][nt][r2] = 0.0f;

    for (int ct = 0; ct < NCHUNK; ++ct) {
        __syncthreads();
        // stage V chunk (B-frag order, k-dim = keys, hi/lo interleaved)
        #pragma unroll
        for (int i = 0; i < 4; ++i) {
            int task = i * TPB + tid;
            int kp = task >> 4, dg = task & 15;
            int key = 2 * kp;
            const float* vp = vbase + (size_t)(ct * 128 + key) * DH + dg * 4;
            float4 va = *(const float4*)(vp);
            float4 vb = *(const float4*)(vp + DH);
            float a4[4] = { va.x, va.y, va.z, va.w };
            float b4[4] = { vb.x, vb.y, vb.z, vb.w };
            int ks = kp >> 3;
            int reg = (kp & 4) ? 1 : 0;
            int tg = kp & 3;
            #pragma unroll
            for (int j = 0; j < 4; ++j) {
                int d = dg * 4 + j;
                int nt = d >> 3;
                float ha = bhi(a4[j]), hb = bhi(b4[j]);
                uint32_t base = KVF_W + (uint32_t)(((nt * 8 + ks) * 32 + (d & 7) * 4 + tg) * 4);
                smw[base + reg]     = bpack(ha, hb);
                smw[base + 2 + reg] = bpack(a4[j] - ha, b4[j] - hb);
            }
        }
        __syncthreads();

        #pragma unroll
        for (int ksl = 0; ksl < 4; ++ksl) {
            int ks = wc * 4 + ksl;
            uint32_t ah[2][4], al[2][4];
            #pragma unroll
            for (int mt = 0; mt < 2; ++mt) {
                float* ar0 = attn0 + (size_t)(r0 + mt * 16 + g) * SEQ + ct * 128 + ks * 16;
                float* ar1 = ar0 + (size_t)8 * SEQ;
                float2 s0 = *(const float2*)(ar0 + 2 * tig);
                float2 s1 = *(const float2*)(ar1 + 2 * tig);
                float2 s2 = *(const float2*)(ar0 + 2 * tig + 8);
                float2 s3 = *(const float2*)(ar1 + 2 * tig + 8);
                float2 p0, p1, p2, p3;
                p0.x = __expf(s0.x - rs[mt][0].x) * rs[mt][0].y;
                p0.y = __expf(s0.y - rs[mt][0].x) * rs[mt][0].y;
                p1.x = __expf(s1.x - rs[mt][1].x) * rs[mt][1].y;
                p1.y = __expf(s1.y - rs[mt][1].x) * rs[mt][1].y;
                p2.x = __expf(s2.x - rs[mt][0].x) * rs[mt][0].y;
                p2.y = __expf(s2.y - rs[mt][0].x) * rs[mt][0].y;
                p3.x = __expf(s3.x - rs[mt][1].x) * rs[mt][1].y;
                p3.y = __expf(s3.y - rs[mt][1].x) * rs[mt][1].y;
                *(float2*)(ar0 + 2 * tig)     = p0;
                *(float2*)(ar1 + 2 * tig)     = p1;
                *(float2*)(ar0 + 2 * tig + 8) = p2;
                *(float2*)(ar1 + 2 * tig + 8) = p3;
                float h0x = bhi(p0.x), h0y = bhi(p0.y), h1x = bhi(p1.x), h1y = bhi(p1.y);
                float h2x = bhi(p2.x), h2y = bhi(p2.y), h3x = bhi(p3.x), h3y = bhi(p3.y);
                ah[mt][0] = bpack(h0x, h0y); ah[mt][1] = bpack(h1x, h1y);
                ah[mt][2] = bpack(h2x, h2y); ah[mt][3] = bpack(h3x, h3y);
                al[mt][0] = bpack(p0.x - h0x, p0.y - h0y);
                al[mt][1] = bpack(p1.x - h1x, p1.y - h1y);
                al[mt][2] = bpack(p2.x - h2x, p2.y - h2y);
                al[mt][3] = bpack(p3.x - h3x, p3.y - h3y);
            }
            #pragma unroll
            for (int nt = 0; nt < 8; ++nt) {
                uint4 bb = *(const uint4*)&smw[KVF_W +
                    (uint32_t)(((nt * 8 + ks) * 32 + lane) * 4)];
                #pragma unroll
                for (int mt = 0; mt < 2; ++mt) {
                    mma_bf16(oacc[mt][nt], ah[mt][0], ah[mt][1], ah[mt][2], ah[mt][3],
                             bb.x, bb.y);
                    mma_bf16(oacc[mt][nt], ah[mt][0], ah[mt][1], ah[mt][2], ah[mt][3],
                             bb.z, bb.w);
                    mma_bf16(oacc[mt][nt], al[mt][0], al[mt][1], al[mt][2], al[mt][3],
                             bb.x, bb.y);
                }
            }
        }
    }

    // ---- O reduction across the two key-groups (reuse KVF region as [128][64])
    float* obuf = &smf[KVF_W];
    __syncthreads();
    if (wc == 1) {
        #pragma unroll
        for (int mt = 0; mt < 2; ++mt) {
            int rA = r0 + mt * 16 + g;
            #pragma unroll
            for (int nt = 0; nt < 8; ++nt) {
                int col = nt * 8 + 2 * tig;
                *(float2*)&obuf[rA * 64 + col]       = make_float2(oacc[mt][nt][0], oacc[mt][nt][1]);
                *(float2*)&obuf[(rA + 8) * 64 + col] = make_float2(oacc[mt][nt][2], oacc[mt][nt][3]);
            }
        }
    }
    __syncthreads();
    if (wc == 0) {
        #pragma unroll
        for (int mt = 0; mt < 2; ++mt) {
            int rA = r0 + mt * 16 + g;
            float* orow0 = out + ((size_t)bh * SEQ + q0 + rA) * DH;
            float* orow1 = orow0 + (size_t)8 * DH;
            #pragma unroll
            for (int nt = 0; nt < 8; ++nt) {
                int col = nt * 8 + 2 * tig;
                float2 u0 = *(const float2*)&obuf[rA * 64 + col];
                float2 u1 = *(const float2*)&obuf[(rA + 8) * 64 + col];
                *(float2*)(orow0 + col) = make_float2(oacc[mt][nt][0] + u0.x,
                                                      oacc[mt][nt][1] + u0.y);
                *(float2*)(orow1 + col) = make_float2(oacc[mt][nt][2] + u1.x,
                                                      oacc[mt][nt][3] + u1.y);
            }
        }
    }
}

extern "C" void kernel_launch(void* const* d_in, const int* in_sizes, int n_in,
                              void* d_out, int out_size)
{
    (void)in_sizes; (void)n_in; (void)out_size;
    const float* q        = (const float*)d_in[0];
    const float* k        = (const float*)d_in[1];
    const float* v        = (const float*)d_in[2];
    const float* add_attn = (const float*)d_in[3];
    const int*   mask     = (const int*)d_in[4];

    float* out  = (float*)d_out;
    float* attn = out + (size_t)4 * 16 * 1024 * 64;

    cudaFuncSetAttribute(attn_flash_kernel,
                         cudaFuncAttributeMaxDynamicSharedMemorySize, SM_BYTES);

    dim3 grid(SEQ / BM, 4 * 16);   // (8, 64)
    attn_flash_kernel<<<grid, TPB, SM_BYTES>>>(q, k, v, add_attn, mask, out, attn);
}

// round 8
// speedup vs baseline: 2.5561x; 2.5561x over previous
#include <cuda_runtime.h>
#include <cuda_fp16.h>
#include <cstdint>

// B=4, H=16, S=1024, D=64 fp32. out buffer: out [B,H,S,D] then attn [B,H,S,S]
#define SEQ 1024
#define DH  64
#define BM  128
#define TPB 256
#define NCHUNK 8

// smem word offsets
#define KVF_W 0        // K frags [16nt][4ks][32][4] / V frags [8nt][8ks][32][4] = 8192 w
#define MFL_W 8192     // mask flags [1024]
#define RED_W 9216     // per-wc (m,l) float2 [2][128] = 512 w
#define RST_W 9728     // rowstat (m, 1/l) float2 [128] = 256 w
#define SM_WORDS 9984
#define SM_BYTES (SM_WORDS * 4)

__device__ __forceinline__ uint32_t hpack(float lo, float hi) {
    uint32_t u;
    asm("cvt.rn.f16x2.f32 %0, %1, %2;" : "=r"(u) : "f"(hi), "f"(lo));
    return u;
}
__device__ __forceinline__ float hhi(float x) {
    return __half2float(__float2half_rn(x));
}
__device__ __forceinline__ void mma_f16(float* d, uint32_t a0, uint32_t a1,
                                        uint32_t a2, uint32_t a3,
                                        uint32_t b0, uint32_t b1) {
    asm volatile(
        "mma.sync.aligned.m16n8k16.row.col.f32.f16.f16.f32 "
        "{%0,%1,%2,%3},{%4,%5,%6,%7},{%8,%9},{%0,%1,%2,%3};"
        : "+f"(d[0]), "+f"(d[1]), "+f"(d[2]), "+f"(d[3])
        : "r"(a0), "r"(a1), "r"(a2), "r"(a3), "r"(b0), "r"(b1));
}

__global__ __launch_bounds__(TPB, 2)
void attn_fp16_kernel(const float* __restrict__ q,
                      const float* __restrict__ k,
                      const float* __restrict__ v,
                      const float* __restrict__ add_attn,
                      const int*   __restrict__ mask,
                      float* __restrict__ out,
                      float* __restrict__ attn)
{
    extern __shared__ uint32_t smw[];
    float* smf = reinterpret_cast<float*>(smw);

    const int tid  = threadIdx.x;
    const int w    = tid >> 5;
    const int lane = tid & 31;
    const int g    = lane >> 2;
    const int tig  = lane & 3;
    const int wr   = w >> 1;            // pass A: row group (32 rows)
    const int wc   = w & 1;             // pass A: key slot within sweep
    const int bh   = blockIdx.y;
    const int b    = bh >> 4;
    const int q0   = blockIdx.x * BM;
    const int r0   = wr * 32;

    const float* qbase = q + ((size_t)bh * SEQ + q0) * DH;
    const float* kbase = k + (size_t)bh * SEQ * DH;
    const float* vbase = v + (size_t)bh * SEQ * DH;
    const float* bias0 = add_attn + (size_t)b * SEQ * SEQ + (size_t)q0 * SEQ;
    float* attn0 = attn + ((size_t)bh * SEQ + q0) * SEQ;

    // ---- mask flags ----
    for (int i = tid; i < SEQ; i += TPB)
        smf[MFL_W + i] = mask[b * SEQ + i] ? 1.0f : 0.0f;

    // ---- Q hi A-fragments in regs (M=32: 2 row-blocks), fp16, scale folded ----
    uint4 qh[2][4];
    #pragma unroll
    for (int mt = 0; mt < 2; ++mt) {
        const float* qr0 = qbase + (size_t)(r0 + mt * 16 + g) * DH;
        const float* qr1 = qr0 + (size_t)8 * DH;
        #pragma unroll
        for (int ks = 0; ks < 4; ++ks) {
            float2 x0 = *(const float2*)(qr0 + ks * 16 + 2 * tig);
            float2 x1 = *(const float2*)(qr1 + ks * 16 + 2 * tig);
            float2 x2 = *(const float2*)(qr0 + ks * 16 + 2 * tig + 8);
            float2 x3 = *(const float2*)(qr1 + ks * 16 + 2 * tig + 8);
            qh[mt][ks].x = hpack(hhi(x0.x * 0.125f), hhi(x0.y * 0.125f));
            qh[mt][ks].y = hpack(hhi(x1.x * 0.125f), hhi(x1.y * 0.125f));
            qh[mt][ks].z = hpack(hhi(x2.x * 0.125f), hhi(x2.y * 0.125f));
            qh[mt][ks].w = hpack(hhi(x3.x * 0.125f), hhi(x3.y * 0.125f));
        }
    }

    float om[2][2], ol[2][2];
    #pragma unroll
    for (int mt = 0; mt < 2; ++mt)
        #pragma unroll
        for (int h = 0; h < 2; ++h) { om[mt][h] = -3.0e38f; ol[mt][h] = 0.0f; }

    // ================= Pass A: S = QK^T + bias, masked -> attn; online (m,l)
    for (int ct = 0; ct < NCHUNK; ++ct) {
        __syncthreads();
        // stage K chunk: direct B-frag build, 1 STS.128 per task
        #pragma unroll
        for (int i = 0; i < 8; ++i) {
            int task = i * TPB + tid;
            int lt = task & 31, ks = (task >> 5) & 3, nt = task >> 7;
            int gt = lt >> 2, tt = lt & 3;
            const float* kp = kbase + (size_t)(ct * 128 + nt * 8 + gt) * DH
                            + ks * 16 + 2 * tt;
            float2 k01 = *(const float2*)kp;
            float2 k89 = *(const float2*)(kp + 8);
            float h0 = hhi(k01.x), h1 = hhi(k01.y);
            float h8 = hhi(k89.x), h9 = hhi(k89.y);
            uint4 u;
            u.x = hpack(h0, h1);
            u.y = hpack(h8, h9);
            u.z = hpack(k01.x - h0, k01.y - h1);
            u.w = hpack(k89.x - h8, k89.y - h9);
            *(uint4*)&smw[KVF_W + (uint32_t)(((nt * 4 + ks) * 32 + lt) * 4)] = u;
        }
        __syncthreads();

        // two 64-key sweeps; warp handles 32 keys (4 nt) per sweep
        #pragma unroll 1
        for (int s2 = 0; s2 < 2; ++s2) {
            const int ntb = s2 * 8 + wc * 4;
            float sacc[2][4][4];
            #pragma unroll
            for (int mt = 0; mt < 2; ++mt)
                #pragma unroll
                for (int ntl = 0; ntl < 4; ++ntl)
                    #pragma unroll
                    for (int r2 = 0; r2 < 4; ++r2) sacc[mt][ntl][r2] = 0.0f;

            #pragma unroll
            for (int ks = 0; ks < 4; ++ks)
                #pragma unroll
                for (int ntl = 0; ntl < 4; ++ntl) {
                    uint4 bb = *(const uint4*)&smw[KVF_W +
                        (uint32_t)((((ntb + ntl) * 4 + ks) * 32 + lane) * 4)];
                    #pragma unroll
                    for (int mt = 0; mt < 2; ++mt) {
                        mma_f16(sacc[mt][ntl], qh[mt][ks].x, qh[mt][ks].y,
                                qh[mt][ks].z, qh[mt][ks].w, bb.x, bb.y);
                        mma_f16(sacc[mt][ntl], qh[mt][ks].x, qh[mt][ks].y,
                                qh[mt][ks].z, qh[mt][ks].w, bb.z, bb.w);
                    }
                }

            // epilogue: bias + mask, write raw s, online (m,l)
            #pragma unroll
            for (int mt = 0; mt < 2; ++mt) {
                int rA = r0 + mt * 16 + g;
                float ml0 = -3.0e38f, ml1 = -3.0e38f;
                #pragma unroll
                for (int ntl = 0; ntl < 4; ++ntl) {
                    int gc = ct * 128 + (ntb + ntl) * 8 + 2 * tig;
                    float2 mf = *(const float2*)&smf[MFL_W + gc];
                    float2 b0 = *(const float2*)(bias0 + (size_t)rA * SEQ + gc);
                    float2 b1 = *(const float2*)(bias0 + (size_t)(rA + 8) * SEQ + gc);
                    float s0 = (mf.x != 0.0f) ? sacc[mt][ntl][0] + b0.x : -1e9f;
                    float s1 = (mf.y != 0.0f) ? sacc[mt][ntl][1] + b0.y : -1e9f;
                    float s2v = (mf.x != 0.0f) ? sacc[mt][ntl][2] + b1.x : -1e9f;
                    float s3 = (mf.y != 0.0f) ? sacc[mt][ntl][3] + b1.y : -1e9f;
                    *(float2*)(attn0 + (size_t)rA * SEQ + gc)       = make_float2(s0, s1);
                    *(float2*)(attn0 + (size_t)(rA + 8) * SEQ + gc) = make_float2(s2v, s3);
                    sacc[mt][ntl][0] = s0; sacc[mt][ntl][1] = s1;
                    sacc[mt][ntl][2] = s2v; sacc[mt][ntl][3] = s3;
                    ml0 = fmaxf(ml0, fmaxf(s0, s1));
                    ml1 = fmaxf(ml1, fmaxf(s2v, s3));
                }
                float mn0 = fmaxf(om[mt][0], ml0), mn1 = fmaxf(om[mt][1], ml1);
                float a0 = 0.0f, a1 = 0.0f;
                #pragma unroll
                for (int ntl = 0; ntl < 4; ++ntl) {
                    a0 += __expf(sacc[mt][ntl][0] - mn0) + __expf(sacc[mt][ntl][1] - mn0);
                    a1 += __expf(sacc[mt][ntl][2] - mn1) + __expf(sacc[mt][ntl][3] - mn1);
                }
                ol[mt][0] = ol[mt][0] * __expf(om[mt][0] - mn0) + a0;  om[mt][0] = mn0;
                ol[mt][1] = ol[mt][1] * __expf(om[mt][1] - mn1) + a1;  om[mt][1] = mn1;
            }
        }
    }

    // ---- merge (m,l): tig lanes, then the two wc slots via smem ----
    #pragma unroll
    for (int mt = 0; mt < 2; ++mt)
        #pragma unroll
        for (int h = 0; h < 2; ++h) {
            float m = om[mt][h], l = ol[mt][h];
            #pragma unroll
            for (int o = 1; o <= 2; o <<= 1) {
                float mo = __shfl_xor_sync(~0u, m, o);
                float lo_ = __shfl_xor_sync(~0u, l, o);
                float mn = fmaxf(m, mo);
                l = l * __expf(m - mn) + lo_ * __expf(mo - mn);
                m = mn;
            }
            if (tig == 0) {
                int row = r0 + mt * 16 + g + 8 * h;
                *(float2*)&smf[RED_W + (wc * 128 + row) * 2] = make_float2(m, l);
            }
        }
    __syncthreads();
    if (tid < 128) {
        float2 a = *(const float2*)&smf[RED_W + tid * 2];
        float2 c = *(const float2*)&smf[RED_W + (128 + tid) * 2];
        float mn = fmaxf(a.x, c.x);
        float l  = a.y * __expf(a.x - mn) + c.y * __expf(c.x - mn);
        *(float2*)&smf[RST_W + tid * 2] = make_float2(mn, 1.0f / l);
    }
    __syncthreads();

    // ================= Pass B: p -> attn; O = P @ V (M=16 per warp) =========
    const int r0b = w * 16;
    const float2 rs0 = *(const float2*)&smf[RST_W + (r0b + g) * 2];
    const float2 rs1 = *(const float2*)&smf[RST_W + (r0b + g + 8) * 2];

    float oacc[8][4];
    #pragma unroll
    for (int nt = 0; nt < 8; ++nt)
        #pragma unroll
        for (int r2 = 0; r2 < 4; ++r2) oacc[nt][r2] = 0.0f;

    for (int ct = 0; ct < NCHUNK; ++ct) {
        __syncthreads();
        // stage V chunk: direct B-frag build, 1 STS.128 per task
        #pragma unroll
        for (int i = 0; i < 8; ++i) {
            int task = i * TPB + tid;
            int lt = task & 31, ks = (task >> 5) & 7, nt = task >> 8;
            int gt = lt >> 2, tt = lt & 3;
            int d  = nt * 8 + gt;
            const float* vp = vbase + (size_t)(ct * 128 + ks * 16 + 2 * tt) * DH + d;
            float v0 = vp[0];
            float v1 = vp[DH];
            float v8 = vp[8 * DH];
            float v9 = vp[9 * DH];
            float h0 = hhi(v0), h1 = hhi(v1), h8 = hhi(v8), h9 = hhi(v9);
            uint4 u;
            u.x = hpack(h0, h1);
            u.y = hpack(h8, h9);
            u.z = hpack(v0 - h0, v1 - h1);
            u.w = hpack(v8 - h8, v9 - h9);
            *(uint4*)&smw[KVF_W + (uint32_t)(((nt * 8 + ks) * 32 + lt) * 4)] = u;
        }
        __syncthreads();

        #pragma unroll
        for (int ks = 0; ks < 8; ++ks) {
            float* ar0 = attn0 + (size_t)(r0b + g) * SEQ + ct * 128 + ks * 16;
            float* ar1 = ar0 + (size_t)8 * SEQ;
            float2 s0 = *(const float2*)(ar0 + 2 * tig);
            float2 s1 = *(const float2*)(ar1 + 2 * tig);
            float2 s2 = *(const float2*)(ar0 + 2 * tig + 8);
            float2 s3 = *(const float2*)(ar1 + 2 * tig + 8);
            float2 p0, p1, p2, p3;
            p0.x = __expf(s0.x - rs0.x) * rs0.y;  p0.y = __expf(s0.y - rs0.x) * rs0.y;
            p1.x = __expf(s1.x - rs1.x) * rs1.y;  p1.y = __expf(s1.y - rs1.x) * rs1.y;
            p2.x = __expf(s2.x - rs0.x) * rs0.y;  p2.y = __expf(s2.y - rs0.x) * rs0.y;
            p3.x = __expf(s3.x - rs1.x) * rs1.y;  p3.y = __expf(s3.y - rs1.x) * rs1.y;
            *(float2*)(ar0 + 2 * tig)     = p0;
            *(float2*)(ar1 + 2 * tig)     = p1;
            *(float2*)(ar0 + 2 * tig + 8) = p2;
            *(float2*)(ar1 + 2 * tig + 8) = p3;
            uint32_t a0 = hpack(hhi(p0.x), hhi(p0.y));
            uint32_t a1 = hpack(hhi(p1.x), hhi(p1.y));
            uint32_t a2 = hpack(hhi(p2.x), hhi(p2.y));
            uint32_t a3 = hpack(hhi(p3.x), hhi(p3.y));
            #pragma unroll
            for (int nt = 0; nt < 8; ++nt) {
                uint4 bb = *(const uint4*)&smw[KVF_W +
                    (uint32_t)(((nt * 8 + ks) * 32 + lane) * 4)];
                mma_f16(oacc[nt], a0, a1, a2, a3, bb.x, bb.y);
                mma_f16(oacc[nt], a0, a1, a2, a3, bb.z, bb.w);
            }
        }
    }

    // ---- write O directly ----
    {
        float* orow0 = out + ((size_t)bh * SEQ + q0 + r0b + g) * DH;
        float* orow1 = orow0 + (size_t)8 * DH;
        #pragma unroll
        for (int nt = 0; nt < 8; ++nt) {
            int col = nt * 8 + 2 * tig;
            *(float2*)(orow0 + col) = make_float2(oacc[nt][0], oacc[nt][1]);
            *(float2*)(orow1 + col) = make_float2(oacc[nt][2], oacc[nt][3]);
        }
    }
}

extern "C" void kernel_launch(void* const* d_in, const int* in_sizes, int n_in,
                              void* d_out, int out_size)
{
    (void)in_sizes; (void)n_in; (void)out_size;
    const float* q        = (const float*)d_in[0];
    const float* k        = (const float*)d_in[1];
    const float* v        = (const float*)d_in[2];
    const float* add_attn = (const float*)d_in[3];
    const int*   mask     = (const int*)d_in[4];

    float* out  = (float*)d_out;
    float* attn = out + (size_t)4 * 16 * 1024 * 64;

    cudaFuncSetAttribute(attn_fp16_kernel,
                         cudaFuncAttributeMaxDynamicSharedMemorySize, SM_BYTES);

    dim3 grid(SEQ / BM, 4 * 16);   // (8, 64)
    attn_fp16_kernel<<<grid, TPB, SM_BYTES>>>(q, k, v, add_attn, mask, out, attn);
}